// round 16
// baseline (speedup 1.0000x reference)
#include <cuda_runtime.h>
#include <cuda_bf16.h>
#include <math.h>

// Problem constants
#define B_  16
#define N_  2048
#define E_  1024
#define G_  2
#define V_  320
#define D_  512
#define GV_ 640
#define M_  (B_ * N_)
#define ROWS_ (M_ * G_)
#define NBLK (ROWS_ / 8)     // 8192 argmax blocks (8 warps each)

#define BK   32
#define NIT  (E_ / BK)       // 32
#define APITCH 40            // bf16 elems per smem row (80B, ldsm conflict-free)
#define THRESH 0.05f

// Dynamic smem: 3 stages x (A 256x40 + B 128x40) bf16
#define STG_BYTES  30720
#define SMEM_TOTAL 92160

// Device scratch (sanctioned: __device__ globals)
__device__ __nv_bfloat16 g_xb[(size_t)M_ * E_];   // x bf16
__device__ __nv_bfloat16 g_wt[(size_t)GV_ * E_];  // W^T bf16 [n][k]
__device__ float         g_wtf[(size_t)GV_ * E_]; // W^T fp32 [n][k] (rescue)
__device__ __nv_bfloat16 g_hb[(size_t)M_ * GV_];  // logits bf16 (42 MB)
__device__ int           g_counts[B_ * G_ * V_];
__device__ int           g_done;                  // last-block counter

// ---------------------------------------------------------------------------
// PTX helpers
// ---------------------------------------------------------------------------
__device__ __forceinline__ unsigned smem_u32(const void* p) {
    unsigned a;
    asm("{ .reg .u64 t; cvta.to.shared.u64 t, %1; cvt.u32.u64 %0, t; }"
        : "=r"(a) : "l"(p));
    return a;
}
__device__ __forceinline__ void cp_async16(unsigned dst, const void* src) {
    asm volatile("cp.async.cg.shared.global [%0], [%1], 16;" :: "r"(dst), "l"(src));
}
__device__ __forceinline__ void cp_commit() {
    asm volatile("cp.async.commit_group;" ::: "memory");
}
__device__ __forceinline__ void cp_wait0() { asm volatile("cp.async.wait_group 0;" ::: "memory"); }
__device__ __forceinline__ void cp_wait1() { asm volatile("cp.async.wait_group 1;" ::: "memory"); }

__device__ __forceinline__ void ldsm4(unsigned* r, unsigned addr) {
    asm volatile("ldmatrix.sync.aligned.m8n8.x4.shared.b16 {%0,%1,%2,%3}, [%4];"
                 : "=r"(r[0]), "=r"(r[1]), "=r"(r[2]), "=r"(r[3]) : "r"(addr));
}
__device__ __forceinline__ void mma16816(float* c, const unsigned* a,
                                         unsigned b0, unsigned b1) {
    asm volatile(
        "mma.sync.aligned.m16n8k16.row.col.f32.bf16.bf16.f32 "
        "{%0,%1,%2,%3}, {%4,%5,%6,%7}, {%8,%9}, {%0,%1,%2,%3};"
        : "+f"(c[0]), "+f"(c[1]), "+f"(c[2]), "+f"(c[3])
        : "r"(a[0]), "r"(a[1]), "r"(a[2]), "r"(a[3]), "r"(b0), "r"(b1));
}

// Issue one k-tile: 2 A rows + 1 B row chunk per thread (3 x 16B)
__device__ __forceinline__ void issue_tile(unsigned dA, unsigned dB,
                                           const __nv_bfloat16* ag,
                                           const __nv_bfloat16* bg) {
    cp_async16(dA,         ag);
    cp_async16(dA + 10240, ag + (size_t)128 * E_);   // rows +128
    cp_async16(dB,         bg);
    cp_commit();
}

// ---------------------------------------------------------------------------
// Kernel 1 (merged prep): zero counts/done + convert W^T (bf16+fp32) + x.
// ---------------------------------------------------------------------------
__global__ __launch_bounds__(256)
void prep_kernel(const float* __restrict__ x, const float* __restrict__ W) {
    const int i = blockIdx.x * blockDim.x + threadIdx.x;

    if (i == 0) g_done = 0;
    if (i < B_ * G_ * V_) g_counts[i] = 0;

    if (i < GV_ * E_) {
        const int n = i >> 10;
        const int k = i & 1023;
        const float w = W[(size_t)k * GV_ + n];
        g_wt[i]  = __float2bfloat16(w);
        g_wtf[i] = w;
    }

    const int n4 = M_ * E_ / 4;
    if (i < n4) {
        float4 v = ((const float4*)x)[i];
        union { __nv_bfloat16 h[4]; uint2 u; } pk;
        pk.h[0] = __float2bfloat16(v.x);
        pk.h[1] = __float2bfloat16(v.y);
        pk.h[2] = __float2bfloat16(v.z);
        pk.h[3] = __float2bfloat16(v.w);
        ((uint2*)g_xb)[i] = pk.u;
    }
}

// ---------------------------------------------------------------------------
// Kernel 2: bf16 tensor-core GEMM h = x @ W (f32 accum, bf16 store).
// BM=256, BN=128, BK=32; 512 thr = 16 warps (4 x 4), warp tile 64x32.
// 3-stage cp.async pipeline. (R6-proven: 142 us, tensor 49.6% = pipe cap.)
// ---------------------------------------------------------------------------
__global__ __launch_bounds__(512, 1)
void mma_gemm_kernel() {
    extern __shared__ __align__(16) __nv_bfloat16 smem[];

    const int tid  = threadIdx.x;
    const int lane = tid & 31;
    const int wid  = tid >> 5;           // 0..15
    const int bm = blockIdx.y * 256;
    const int bn = blockIdx.x * 128;
    const int wm = (wid & 3) * 64;
    const int wn = (wid >> 2) * 32;

    const int arow  = tid >> 2;          // 0..127
    const int acoff = (tid & 3) * 8;     // 0,8,16,24

    const __nv_bfloat16* ag = g_xb + (size_t)(bm + arow) * E_ + acoff;
    const __nv_bfloat16* bg = g_wt + (size_t)(bn + arow) * E_ + acoff;

    const unsigned sBase = smem_u32(&smem[0]);
    const unsigned dA = sBase + (unsigned)(arow * APITCH + acoff) * 2u;
    const unsigned dB = sBase + 20480u + (unsigned)(arow * APITCH + acoff) * 2u;

    float acc[4][4][4];
    for (int i = 0; i < 4; i++)
        for (int j = 0; j < 4; j++)
            for (int k = 0; k < 4; k++)
                acc[i][j][k] = 0.0f;

    issue_tile(dA, dB, ag, bg);
    issue_tile(dA + STG_BYTES, dB + STG_BYTES, ag + BK, bg + BK);

    const int arow_f = wm + (lane & 15);
    const int acol_f = (lane >> 4) * 8;
    const unsigned aBase = sBase + (unsigned)(arow_f * APITCH + acol_f) * 2u;
    const int brow_f = wn + (lane & 7) + ((lane >> 4) << 3);
    const int bcol_f = ((lane >> 3) & 1) * 8;
    const unsigned bBase = sBase + 20480u + (unsigned)(brow_f * APITCH + bcol_f) * 2u;

    for (int it = 0; it < NIT; ++it) {
        const int s = it % 3;
        if (it == NIT - 1) cp_wait0(); else cp_wait1();
        __syncthreads();

        if (it + 2 < NIT) {
            const int s2 = (it + 2) % 3;
            issue_tile(dA + (unsigned)(s2 * STG_BYTES),
                       dB + (unsigned)(s2 * STG_BYTES),
                       ag + (it + 2) * BK, bg + (it + 2) * BK);
        }

        const unsigned so = (unsigned)(s * STG_BYTES);
#pragma unroll
        for (int kk = 0; kk < 2; ++kk) {
            unsigned af[4][4];
            unsigned bf[2][4];
#pragma unroll
            for (int mi = 0; mi < 4; ++mi)
                ldsm4(af[mi], aBase + so + (unsigned)(mi * 16 * APITCH + kk * 16) * 2u);
#pragma unroll
            for (int p = 0; p < 2; ++p)
                ldsm4(bf[p], bBase + so + (unsigned)(p * 16 * APITCH + kk * 16) * 2u);
#pragma unroll
            for (int mi = 0; mi < 4; ++mi) {
#pragma unroll
                for (int p = 0; p < 2; ++p) {
                    mma16816(acc[mi][2 * p],     af[mi], bf[p][0], bf[p][1]);
                    mma16816(acc[mi][2 * p + 1], af[mi], bf[p][2], bf[p][3]);
                }
            }
        }
    }

    // Epilogue: f32 acc -> bf16x2 stores
    const int cg = lane >> 2;
    const int tg = lane & 3;
#pragma unroll
    for (int mi = 0; mi < 4; ++mi) {
        const int row = bm + wm + mi * 16 + cg;
        __nv_bfloat162* o0 =
            (__nv_bfloat162*)(g_hb + (size_t)row * GV_ + bn + wn + tg * 2);
        __nv_bfloat162* o1 =
            (__nv_bfloat162*)(g_hb + (size_t)(row + 8) * GV_ + bn + wn + tg * 2);
#pragma unroll
        for (int ni = 0; ni < 4; ++ni) {
            float2 v0; v0.x = acc[mi][ni][0]; v0.y = acc[mi][ni][1];
            float2 v1; v1.x = acc[mi][ni][2]; v1.y = acc[mi][ni][3];
            o0[ni * 4] = __float22bfloat162_rn(v0);
            o1[ni * 4] = __float22bfloat162_rn(v1);
        }
    }
}

// ---------------------------------------------------------------------------
// Kernel 3: argmax + exact rescue + histogram + gather + last-block entropy.
// One warp per (b,n,g) row; grid exactly NBLK blocks of 8 warps.
// ---------------------------------------------------------------------------
__global__ __launch_bounds__(256)
void argmax_gather_kernel(const float* __restrict__ x,
                          const float* __restrict__ u,
                          const float* __restrict__ bias,
                          const float* __restrict__ codebook,
                          float* __restrict__ out, int out_size) {
    const int wid  = threadIdx.x >> 5;
    const int lane = threadIdx.x & 31;
    const int r    = blockIdx.x * 8 + wid;        // < ROWS_ always (exact grid)

    const int gidx = r & 1;
    const __nv_bfloat16* hrow = g_hb + (size_t)r * V_;
    const float* urow = u + (size_t)r * V_;
    const float* brow = bias + gidx * V_;

    const float kA = 1.0f - 2.0f * 1e-7f;
    const float kB = 1e-7f;

    float vals[10];
    float best = -3.4e38f;
    int   bi   = 0;
#pragma unroll
    for (int i = 0; i < 10; i++) {
        const int v = i * 32 + lane;
        float uu = fmaf(urow[v], kA, kB);
        float gn = -__logf(-__logf(uu));          // fast log in scan
        float val = __bfloat162float(hrow[v]) + brow[v] + gn;
        vals[i] = val;
        if (val > best) { best = val; bi = v; }
    }
#pragma unroll
    for (int off = 16; off; off >>= 1) {
        float ov = __shfl_down_sync(0xffffffffu, best, off);
        int   oi = __shfl_down_sync(0xffffffffu, bi, off);
        if (ov > best || (ov == best && oi < bi)) { best = ov; bi = oi; }
    }
    best = __shfl_sync(0xffffffffu, best, 0);
    bi   = __shfl_sync(0xffffffffu, bi, 0);

    float second = -3.4e38f;
#pragma unroll
    for (int i = 0; i < 10; i++) {
        const int v = i * 32 + lane;
        if (v != bi) second = fmaxf(second, vals[i]);
    }
#pragma unroll
    for (int off = 16; off; off >>= 1)
        second = fmaxf(second, __shfl_xor_sync(0xffffffffu, second, off));

    if (best - second < THRESH) {
        const float4* xr4 = (const float4*)(x + (size_t)(r >> 1) * E_);
        float ex_best = -3.4e38f;
        int   ex_bi   = V_;
        const float cut = best - THRESH;
        for (int i = 0; i < 10; i++) {
            unsigned bal = __ballot_sync(0xffffffffu, vals[i] >= cut);
            while (bal) {
                const int j = __ffs(bal) - 1;
                bal &= bal - 1;
                const int vc = i * 32 + j;
                const float4* wr4 =
                    (const float4*)(g_wtf + (size_t)(gidx * V_ + vc) * E_);
                float s0 = 0.0f, s1 = 0.0f, s2 = 0.0f, s3 = 0.0f;
#pragma unroll
                for (int k4 = lane; k4 < 256; k4 += 32) {   // 8 iters, MLP 16
                    float4 xa = xr4[k4];
                    float4 wa = wr4[k4];
                    s0 = fmaf(xa.x, wa.x, s0);
                    s1 = fmaf(xa.y, wa.y, s1);
                    s2 = fmaf(xa.z, wa.z, s2);
                    s3 = fmaf(xa.w, wa.w, s3);
                }
                float s = (s0 + s1) + (s2 + s3);
#pragma unroll
                for (int off = 16; off; off >>= 1)
                    s += __shfl_xor_sync(0xffffffffu, s, off);
                float uu = fmaf(urow[vc], kA, kB);
                float ex = s + brow[vc] + (-logf(-logf(uu)));   // exact log
                if (ex > ex_best || (ex == ex_best && vc < ex_bi)) {
                    ex_best = ex;
                    ex_bi   = vc;
                }
            }
        }
        bi = ex_bi;
    }

    if (lane == 0) {
        int b = r >> 12;
        atomicAdd(&g_counts[(b * G_ + gidx) * V_ + bi], 1);
    }

    const float4* cb = (const float4*)(codebook + ((size_t)(gidx * V_ + bi)) * D_);
    float4*       op = (float4*)(out + (size_t)r * D_);
#pragma unroll
    for (int i = 0; i < 4; i++)
        op[i * 32 + lane] = cb[i * 32 + lane];

    // ---- Last block computes entropy from the completed histogram ----
    __shared__ int is_last;
    __syncthreads();
    if (threadIdx.x == 0) {
        __threadfence();
        is_last = (atomicAdd(&g_done, 1) == NBLK - 1) ? 1 : 0;
    }
    __syncthreads();
    if (is_last) {
        __shared__ float part[8];
        float ent_acc = 0.0f;
        for (int w = wid; w < 32; w += 8) {      // 4 (b,g) pairs per warp
            const int* c = g_counts + w * V_;
            float cv[10];
            float m = -3.4e38f;
#pragma unroll
            for (int i = 0; i < 10; i++) {
                cv[i] = (float)c[lane + i * 32];
                m = fmaxf(m, cv[i]);
            }
#pragma unroll
            for (int off = 16; off; off >>= 1)
                m = fmaxf(m, __shfl_xor_sync(0xffffffffu, m, off));
            float s = 0.0f;
#pragma unroll
            for (int i = 0; i < 10; i++)
                s += expf(cv[i] - m);
#pragma unroll
            for (int off = 16; off; off >>= 1)
                s += __shfl_xor_sync(0xffffffffu, s, off);
            float ent = 0.0f;
#pragma unroll
            for (int i = 0; i < 10; i++) {
                float p = expf(cv[i] - m) / s;
                ent += p * logf(p + 1e-8f);
            }
#pragma unroll
            for (int off = 16; off; off >>= 1)
                ent += __shfl_xor_sync(0xffffffffu, ent, off);
            ent_acc += ent;                      // lane 0 holds warp total
        }
        if (lane == 0) part[wid] = ent_acc;
        __syncthreads();
        if (threadIdx.x == 0) {
            float t = 0.0f;
#pragma unroll
            for (int i = 0; i < 8; i++)
                t += part[i];
            out[out_size - 1] = -t / (float)(G_ * V_);
        }
    }
}

// ---------------------------------------------------------------------------
extern "C" void kernel_launch(void* const* d_in, const int* in_sizes, int n_in,
                              void* d_out, int out_size) {
    const float* x        = (const float*)d_in[0];
    const float* u        = (const float*)d_in[1];
    const float* W        = (const float*)d_in[2];
    const float* bias     = (const float*)d_in[3];
    const float* codebook = (const float*)d_in[4];
    float* out = (float*)d_out;
    (void)in_sizes; (void)n_in;

    cudaFuncSetAttribute(mma_gemm_kernel,
                         cudaFuncAttributeMaxDynamicSharedMemorySize, SMEM_TOTAL);

    prep_kernel<<<(M_ * E_ / 4 + 255) / 256, 256>>>(x, W);

    dim3 gg(GV_ / 128, M_ / 256);   // (5, 128)
    mma_gemm_kernel<<<gg, 512, SMEM_TOTAL>>>();

    argmax_gather_kernel<<<NBLK, 256>>>(x, u, bias, codebook, out, out_size);
}

// round 17
// speedup vs baseline: 1.1582x; 1.1582x over previous
#include <cuda_runtime.h>
#include <cuda_bf16.h>
#include <math.h>

// Problem constants
#define B_  16
#define N_  2048
#define E_  1024
#define G_  2
#define V_  320
#define D_  512
#define GV_ 640
#define M_  (B_ * N_)
#define ROWS_ (M_ * G_)

#define BK   32
#define NIT  (E_ / BK)       // 32
#define APITCH 40            // bf16 elems per smem row (80B, ldsm conflict-free)
#define THRESH 0.05f

// Dynamic smem: 3 stages x (A 256x40 + B 128x40) bf16
#define STG_BYTES  30720
#define SMEM_TOTAL 92160

// Device scratch (sanctioned: __device__ globals)
__device__ __nv_bfloat16 g_wt[(size_t)GV_ * E_];  // W^T bf16 [n][k]
__device__ float         g_wtf[(size_t)GV_ * E_]; // W^T fp32 [n][k] (rescue)
__device__ __nv_bfloat16 g_hb[(size_t)M_ * GV_];  // logits bf16 (42 MB)
__device__ int           g_counts[B_ * G_ * V_];

// ---------------------------------------------------------------------------
// PTX helpers
// ---------------------------------------------------------------------------
__device__ __forceinline__ unsigned smem_u32(const void* p) {
    unsigned a;
    asm("{ .reg .u64 t; cvta.to.shared.u64 t, %1; cvt.u32.u64 %0, t; }"
        : "=r"(a) : "l"(p));
    return a;
}
__device__ __forceinline__ void cp_async16(unsigned dst, const void* src) {
    asm volatile("cp.async.cg.shared.global [%0], [%1], 16;" :: "r"(dst), "l"(src));
}
__device__ __forceinline__ void cp_commit() {
    asm volatile("cp.async.commit_group;" ::: "memory");
}
__device__ __forceinline__ void cp_wait0() { asm volatile("cp.async.wait_group 0;" ::: "memory"); }
__device__ __forceinline__ void cp_wait1() { asm volatile("cp.async.wait_group 1;" ::: "memory"); }

__device__ __forceinline__ void ldsm4(unsigned* r, unsigned addr) {
    asm volatile("ldmatrix.sync.aligned.m8n8.x4.shared.b16 {%0,%1,%2,%3}, [%4];"
                 : "=r"(r[0]), "=r"(r[1]), "=r"(r[2]), "=r"(r[3]) : "r"(addr));
}
__device__ __forceinline__ void mma16816(float* c, const unsigned* a,
                                         unsigned b0, unsigned b1) {
    asm volatile(
        "mma.sync.aligned.m16n8k16.row.col.f32.bf16.bf16.f32 "
        "{%0,%1,%2,%3}, {%4,%5,%6,%7}, {%8,%9}, {%0,%1,%2,%3};"
        : "+f"(c[0]), "+f"(c[1]), "+f"(c[2]), "+f"(c[3])
        : "r"(a[0]), "r"(a[1]), "r"(a[2]), "r"(a[3]), "r"(b0), "r"(b1));
}

// Load 8 f32 and pack to 8 bf16 (uint4)
__device__ __forceinline__ uint4 ldcvt8(const float* p) {
    float4 a = *(const float4*)p;
    float4 b = *(const float4*)(p + 4);
    uint4 r;
    __nv_bfloat162 h;
    h = __float22bfloat162_rn(make_float2(a.x, a.y)); r.x = *(unsigned*)&h;
    h = __float22bfloat162_rn(make_float2(a.z, a.w)); r.y = *(unsigned*)&h;
    h = __float22bfloat162_rn(make_float2(b.x, b.y)); r.z = *(unsigned*)&h;
    h = __float22bfloat162_rn(make_float2(b.z, b.w)); r.w = *(unsigned*)&h;
    return r;
}

// ---------------------------------------------------------------------------
// Kernel 1: tiled W transpose (f32 + bf16 outputs) + zero counts.
// Grid (GV_/32, E_/32), block 32x32. Coalesced read AND write.
// ---------------------------------------------------------------------------
__global__ __launch_bounds__(1024)
void prep_kernel(const float* __restrict__ W) {
    __shared__ float t[32][33];
    const int n0 = blockIdx.x * 32;
    const int k0 = blockIdx.y * 32;
    const int tx = threadIdx.x;
    const int ty = threadIdx.y;

    t[ty][tx] = W[(size_t)(k0 + ty) * GV_ + n0 + tx];   // coalesced in n

    const int gtid = (blockIdx.y * (GV_ / 32) + blockIdx.x) * 1024 + ty * 32 + tx;
    if (gtid < B_ * G_ * V_) g_counts[gtid] = 0;

    __syncthreads();

    const float v = t[tx][ty];                          // W[k0+tx][n0+ty]
    const size_t o = (size_t)(n0 + ty) * E_ + k0 + tx;  // coalesced in k
    g_wtf[o] = v;
    g_wt[o]  = __float2bfloat16(v);
}

// ---------------------------------------------------------------------------
// Kernel 2: bf16 tensor-core GEMM h = x @ W (f32 accum, bf16 store).
// BM=256, BN=128, BK=32; 512 thr = 16 warps (4 x 4), warp tile 64x32.
// A path: LDG f32 -> cvt -> STS (register-prefetched 1 iter ahead).
// B path: cp.async from prep-transposed bf16 W^T. Same 1-sync/iter pipeline.
// ---------------------------------------------------------------------------
__global__ __launch_bounds__(512, 1)
void mma_gemm_kernel(const float* __restrict__ x) {
    extern __shared__ __align__(16) unsigned char dsm[];

    const int tid  = threadIdx.x;
    const int lane = tid & 31;
    const int wid  = tid >> 5;           // 0..15
    const int bm = blockIdx.y * 256;
    const int bn = blockIdx.x * 128;
    const int wm = (wid & 3) * 64;
    const int wn = (wid >> 2) * 32;

    const int arow  = tid >> 2;          // 0..127
    const int acoff = (tid & 3) * 8;     // 0,8,16,24

    const float* aLo = x + (size_t)(bm + arow) * E_ + acoff;
    const float* aHi = aLo + (size_t)128 * E_;
    const __nv_bfloat16* bg = g_wt + (size_t)(bn + arow) * E_ + acoff;

    const unsigned sBase = smem_u32(dsm);
    const unsigned aDstOff = (unsigned)(arow * APITCH + acoff) * 2u;
    const unsigned dB = sBase + 20480u + aDstOff;

    float acc[4][4][4];
    for (int i = 0; i < 4; i++)
        for (int j = 0; j < 4; j++)
            for (int k = 0; k < 4; k++)
                acc[i][j][k] = 0.0f;

    // Prologue: stages 0,1 filled directly; regs preloaded for stage 2.
    {
        uint4 lo = ldcvt8(aLo);
        uint4 hi = ldcvt8(aHi);
        *(uint4*)(dsm + aDstOff)         = lo;
        *(uint4*)(dsm + aDstOff + 10240) = hi;
        cp_async16(dB, bg);
        cp_commit();
        lo = ldcvt8(aLo + BK);
        hi = ldcvt8(aHi + BK);
        *(uint4*)(dsm + STG_BYTES + aDstOff)         = lo;
        *(uint4*)(dsm + STG_BYTES + aDstOff + 10240) = hi;
        cp_async16(dB + STG_BYTES, bg + BK);
        cp_commit();
    }
    uint4 pLo = ldcvt8(aLo + 2 * BK);
    uint4 pHi = ldcvt8(aHi + 2 * BK);

    const int arow_f = wm + (lane & 15);
    const int acol_f = (lane >> 4) * 8;
    const unsigned aBase = sBase + (unsigned)(arow_f * APITCH + acol_f) * 2u;
    const int brow_f = wn + (lane & 7) + ((lane >> 4) << 3);
    const int bcol_f = ((lane >> 3) & 1) * 8;
    const unsigned bBase = sBase + 20480u + (unsigned)(brow_f * APITCH + bcol_f) * 2u;

    for (int it = 0; it < NIT; ++it) {
        const int s = it % 3;
        if (it == NIT - 1) cp_wait0(); else cp_wait1();
        __syncthreads();

        if (it + 2 < NIT) {
            const int s2 = (it + 2) % 3;
            *(uint4*)(dsm + s2 * STG_BYTES + aDstOff)         = pLo;
            *(uint4*)(dsm + s2 * STG_BYTES + aDstOff + 10240) = pHi;
            if (it + 3 < NIT) {
                pLo = ldcvt8(aLo + (it + 3) * BK);
                pHi = ldcvt8(aHi + (it + 3) * BK);
            }
            cp_async16(dB + (unsigned)(s2 * STG_BYTES), bg + (it + 2) * BK);
            cp_commit();
        }

        const unsigned so = (unsigned)(s * STG_BYTES);
#pragma unroll
        for (int kk = 0; kk < 2; ++kk) {
            unsigned af[4][4];
            unsigned bf[2][4];
#pragma unroll
            for (int mi = 0; mi < 4; ++mi)
                ldsm4(af[mi], aBase + so + (unsigned)(mi * 16 * APITCH + kk * 16) * 2u);
#pragma unroll
            for (int p = 0; p < 2; ++p)
                ldsm4(bf[p], bBase + so + (unsigned)(p * 16 * APITCH + kk * 16) * 2u);
#pragma unroll
            for (int mi = 0; mi < 4; ++mi) {
#pragma unroll
                for (int p = 0; p < 2; ++p) {
                    mma16816(acc[mi][2 * p],     af[mi], bf[p][0], bf[p][1]);
                    mma16816(acc[mi][2 * p + 1], af[mi], bf[p][2], bf[p][3]);
                }
            }
        }
    }

    // Epilogue: f32 acc -> bf16x2 stores
    const int cg = lane >> 2;
    const int tg = lane & 3;
#pragma unroll
    for (int mi = 0; mi < 4; ++mi) {
        const int row = bm + wm + mi * 16 + cg;
        __nv_bfloat162* o0 =
            (__nv_bfloat162*)(g_hb + (size_t)row * GV_ + bn + wn + tg * 2);
        __nv_bfloat162* o1 =
            (__nv_bfloat162*)(g_hb + (size_t)(row + 8) * GV_ + bn + wn + tg * 2);
#pragma unroll
        for (int ni = 0; ni < 4; ++ni) {
            float2 v0; v0.x = acc[mi][ni][0]; v0.y = acc[mi][ni][1];
            float2 v1; v1.x = acc[mi][ni][2]; v1.y = acc[mi][ni][3];
            o0[ni * 4] = __float22bfloat162_rn(v0);
            o1[ni * 4] = __float22bfloat162_rn(v1);
        }
    }
}

// ---------------------------------------------------------------------------
// Kernel 3: argmax + exact rescue + histogram + gather. One warp per row.
// Scan: __logf (MUFU). Rescue: exact fp32 logf + float4 dot (MLP 16).
// ---------------------------------------------------------------------------
__global__ __launch_bounds__(256)
void argmax_gather_kernel(const float* __restrict__ x,
                          const float* __restrict__ u,
                          const float* __restrict__ bias,
                          const float* __restrict__ codebook,
                          float* __restrict__ out) {
    const int warp = (blockIdx.x * blockDim.x + threadIdx.x) >> 5;
    const int lane = threadIdx.x & 31;
    if (warp >= ROWS_) return;

    const int r    = warp;
    const int gidx = r & 1;
    const __nv_bfloat16* hrow = g_hb + (size_t)r * V_;
    const float* urow = u + (size_t)r * V_;
    const float* brow = bias + gidx * V_;

    const float kA = 1.0f - 2.0f * 1e-7f;
    const float kB = 1e-7f;

    float vals[10];
    float best = -3.4e38f;
    int   bi   = 0;
#pragma unroll
    for (int i = 0; i < 10; i++) {
        const int v = i * 32 + lane;
        float uu = fmaf(urow[v], kA, kB);
        float gn = -__logf(-__logf(uu));          // fast log in scan
        float val = __bfloat162float(hrow[v]) + brow[v] + gn;
        vals[i] = val;
        if (val > best) { best = val; bi = v; }
    }
#pragma unroll
    for (int off = 16; off; off >>= 1) {
        float ov = __shfl_down_sync(0xffffffffu, best, off);
        int   oi = __shfl_down_sync(0xffffffffu, bi, off);
        if (ov > best || (ov == best && oi < bi)) { best = ov; bi = oi; }
    }
    best = __shfl_sync(0xffffffffu, best, 0);
    bi   = __shfl_sync(0xffffffffu, bi, 0);

    float second = -3.4e38f;
#pragma unroll
    for (int i = 0; i < 10; i++) {
        const int v = i * 32 + lane;
        if (v != bi) second = fmaxf(second, vals[i]);
    }
#pragma unroll
    for (int off = 16; off; off >>= 1)
        second = fmaxf(second, __shfl_xor_sync(0xffffffffu, second, off));

    if (best - second < THRESH) {
        const float4* xr4 = (const float4*)(x + (size_t)(r >> 1) * E_);
        float ex_best = -3.4e38f;
        int   ex_bi   = V_;
        const float cut = best - THRESH;
        for (int i = 0; i < 10; i++) {
            unsigned bal = __ballot_sync(0xffffffffu, vals[i] >= cut);
            while (bal) {
                const int j = __ffs(bal) - 1;
                bal &= bal - 1;
                const int vc = i * 32 + j;
                const float4* wr4 =
                    (const float4*)(g_wtf + (size_t)(gidx * V_ + vc) * E_);
                float s0 = 0.0f, s1 = 0.0f, s2 = 0.0f, s3 = 0.0f;
#pragma unroll
                for (int k4 = lane; k4 < 256; k4 += 32) {   // 8 iters, MLP 16
                    float4 xa = xr4[k4];
                    float4 wa = wr4[k4];
                    s0 = fmaf(xa.x, wa.x, s0);
                    s1 = fmaf(xa.y, wa.y, s1);
                    s2 = fmaf(xa.z, wa.z, s2);
                    s3 = fmaf(xa.w, wa.w, s3);
                }
                float s = (s0 + s1) + (s2 + s3);
#pragma unroll
                for (int off = 16; off; off >>= 1)
                    s += __shfl_xor_sync(0xffffffffu, s, off);
                float uu = fmaf(urow[vc], kA, kB);
                float ex = s + brow[vc] + (-logf(-logf(uu)));   // exact log
                if (ex > ex_best || (ex == ex_best && vc < ex_bi)) {
                    ex_best = ex;
                    ex_bi   = vc;
                }
            }
        }
        bi = ex_bi;
    }

    if (lane == 0) {
        int b = r >> 12;
        atomicAdd(&g_counts[(b * G_ + gidx) * V_ + bi], 1);
    }

    const float4* cb = (const float4*)(codebook + ((size_t)(gidx * V_ + bi)) * D_);
    float4*       op = (float4*)(out + (size_t)r * D_);
#pragma unroll
    for (int i = 0; i < 4; i++)
        op[i * 32 + lane] = cb[i * 32 + lane];
}

// ---------------------------------------------------------------------------
// Kernel 4: entropy from histograms (one warp per (b,g)) — R15 version.
// ---------------------------------------------------------------------------
__global__ void entropy_kernel(float* __restrict__ out, int out_size) {
    const int w    = threadIdx.x >> 5;
    const int lane = threadIdx.x & 31;
    const int* c = g_counts + w * V_;

    float cv[10];
    float m = -3.4e38f;
#pragma unroll
    for (int i = 0; i < 10; i++) {
        cv[i] = (float)c[lane + i * 32];
        m = fmaxf(m, cv[i]);
    }
#pragma unroll
    for (int off = 16; off; off >>= 1)
        m = fmaxf(m, __shfl_xor_sync(0xffffffffu, m, off));

    float s = 0.0f;
#pragma unroll
    for (int i = 0; i < 10; i++)
        s += expf(cv[i] - m);
#pragma unroll
    for (int off = 16; off; off >>= 1)
        s += __shfl_xor_sync(0xffffffffu, s, off);

    float ent = 0.0f;
#pragma unroll
    for (int i = 0; i < 10; i++) {
        float p = expf(cv[i] - m) / s;
        ent += p * logf(p + 1e-8f);
    }
#pragma unroll
    for (int off = 16; off; off >>= 1)
        ent += __shfl_xor_sync(0xffffffffu, ent, off);

    __shared__ float part[32];
    if (lane == 0) part[w] = ent;
    __syncthreads();
    if (threadIdx.x == 0) {
        float t = 0.0f;
#pragma unroll
        for (int i = 0; i < 32; i++)
            t += part[i];
        out[out_size - 1] = -t / (float)(G_ * V_);
    }
}

// ---------------------------------------------------------------------------
extern "C" void kernel_launch(void* const* d_in, const int* in_sizes, int n_in,
                              void* d_out, int out_size) {
    const float* x        = (const float*)d_in[0];
    const float* u        = (const float*)d_in[1];
    const float* W        = (const float*)d_in[2];
    const float* bias     = (const float*)d_in[3];
    const float* codebook = (const float*)d_in[4];
    float* out = (float*)d_out;
    (void)in_sizes; (void)n_in;

    cudaFuncSetAttribute(mma_gemm_kernel,
                         cudaFuncAttributeMaxDynamicSharedMemorySize, SMEM_TOTAL);

    dim3 pg(GV_ / 32, E_ / 32);     // (20, 32)
    prep_kernel<<<pg, dim3(32, 32)>>>(W);

    dim3 gg(GV_ / 128, M_ / 256);   // (5, 128)
    mma_gemm_kernel<<<gg, 512, SMEM_TOTAL>>>(x);

    argmax_gather_kernel<<<(ROWS_ * 32 + 255) / 256, 256>>>(x, u, bias, codebook, out);

    entropy_kernel<<<1, 1024>>>(out, out_size);
}